// round 6
// baseline (speedup 1.0000x reference)
#include <cuda_runtime.h>

#define NN 10000
#define NE 160000

#define SILU_C_F   1.6765867f
#define INV_S8     0.35355339059327373f
#define INV_S32    0.17677669529663687f
#define INV_S96    0.10206207261596575f
#define INV_S128   0.08838834764831845f
#define INV_S3     0.57735026918962576f
#define S3_DIV_S5  0.77459666924148338f   // sqrt(3/5)
#define IS2        0.70710678118654752f   // 1/sqrt(2)
#define IS6        0.40824829046386302f   // 1/sqrt(6)
#define C_S        0.38268343236508977f   // sin(pi/8)
#define C_X        0.92387953251128676f   // cos(pi/8)

// scratch
__device__ float g_y[NN * 160];
__device__ float g_s[NN * 160];
__device__ float g_agg[NN * 960];
// transposed weights (column-major so threads read LDG.128)
__device__ float g_w0T[64 * 96];    // lin2_w0^T  [c][p]
__device__ float g_w1T[32 * 128];   // lin2_w1^T
__device__ float g_w2T[32 * 96];    // lin2_w2^T
__device__ float g_l1w0T[64 * 64];  // lin1_w0^T
__device__ float g_scw0T[64 * 64];  // sc_w0^T
__device__ float g_l1w1T[32 * 32];  // lin1_w1^T
__device__ float g_scw1T[32 * 32];  // sc_w1^T

__device__ __forceinline__ void red4(float* p, float a, float b, float c, float d) {
    asm volatile("red.global.add.v4.f32 [%0], {%1,%2,%3,%4};"
                 :: "l"(p), "f"(a), "f"(b), "f"(c), "f"(d) : "memory");
}
__device__ __forceinline__ unsigned long long pack2(float x) {
    unsigned long long r; asm("mov.b64 %0, {%1, %1};" : "=l"(r) : "f"(x)); return r;
}
__device__ __forceinline__ void fma2(unsigned long long& d, unsigned long long a, unsigned long long b) {
    asm("fma.rn.f32x2 %0, %1, %2, %0;" : "+l"(d) : "l"(a), "l"(b));
}
__device__ __forceinline__ float2 unpack2(unsigned long long v) {
    float2 f; asm("mov.b64 {%0, %1}, %2;" : "=f"(f.x), "=f"(f.y) : "l"(v)); return f;
}

// ---------------- zero agg ----------------
__global__ void k_zero() {
    int i = blockIdx.x * blockDim.x + threadIdx.x;
    const int n4 = NN * 960 / 4;
    if (i < n4) reinterpret_cast<float4*>(g_agg)[i] = make_float4(0.f, 0.f, 0.f, 0.f);
}

// ---------------- transpose weights ----------------
__global__ void k_tw(const float* __restrict__ lin2_w0, const float* __restrict__ lin2_w1,
                     const float* __restrict__ lin2_w2, const float* __restrict__ lin1_w0,
                     const float* __restrict__ lin1_w1, const float* __restrict__ sc_w0,
                     const float* __restrict__ sc_w1) {
    int idx = blockIdx.x * blockDim.x + threadIdx.x;
    if (idx < 6144) { int c = idx / 96, p = idx % 96; g_w0T[idx] = lin2_w0[p * 64 + c]; return; }
    idx -= 6144;
    if (idx < 4096) { int c = idx / 128, p = idx % 128; g_w1T[idx] = lin2_w1[p * 32 + c]; return; }
    idx -= 4096;
    if (idx < 3072) { int c = idx / 96, p = idx % 96; g_w2T[idx] = lin2_w2[p * 32 + c]; return; }
    idx -= 3072;
    if (idx < 4096) { int c = idx / 64, u = idx % 64; g_l1w0T[idx] = lin1_w0[u * 64 + c]; return; }
    idx -= 4096;
    if (idx < 4096) { int c = idx / 64, u = idx % 64; g_scw0T[idx] = sc_w0[u * 64 + c]; return; }
    idx -= 4096;
    if (idx < 1024) { int c = idx / 32, u = idx % 32; g_l1w1T[idx] = lin1_w1[u * 32 + c]; return; }
    idx -= 1024;
    if (idx < 1024) { int c = idx / 32, u = idx % 32; g_scw1T[idx] = sc_w1[u * 32 + c]; return; }
}

// ---------------- node pre-linear: y (lin1) and s (sc) ----------------
__global__ __launch_bounds__(160) void k_node(
    const float* __restrict__ node_input, const float* __restrict__ node_attr)
{
    __shared__ float xs[160];
    __shared__ float xsT[96];   // xsT[i*32+u] = x1[u][i]
    int n = blockIdx.x, t = threadIdx.x;
    xs[t] = node_input[n * 160 + t];
    __syncthreads();
    if (t < 96) { int i = t >> 5, u = t & 31; xsT[t] = xs[64 + u * 3 + i]; }
    __syncthreads();
    float a = node_attr[n];
    if (t < 64) {
        float ay = 0.f, as = 0.f;
        #pragma unroll
        for (int u = 0; u < 64; u += 4) {
            float4 xv = *reinterpret_cast<const float4*>(xs + u);
            float4 wy = *reinterpret_cast<const float4*>(g_l1w0T + t * 64 + u);
            float4 ws = *reinterpret_cast<const float4*>(g_scw0T + t * 64 + u);
            ay = fmaf(xv.x, wy.x, fmaf(xv.y, wy.y, fmaf(xv.z, wy.z, fmaf(xv.w, wy.w, ay))));
            as = fmaf(xv.x, ws.x, fmaf(xv.y, ws.y, fmaf(xv.z, ws.z, fmaf(xv.w, ws.w, as))));
        }
        g_y[n * 160 + t] = ay * a * 0.125f;
        g_s[n * 160 + t] = as * a * 0.125f;
    } else {
        int j = t - 64, v = j / 3, i = j - 3 * v;
        float ay = 0.f, as = 0.f;
        #pragma unroll
        for (int u = 0; u < 32; u += 4) {
            float4 xv = *reinterpret_cast<const float4*>(xsT + i * 32 + u);
            float4 wy = *reinterpret_cast<const float4*>(g_l1w1T + v * 32 + u);
            float4 ws = *reinterpret_cast<const float4*>(g_scw1T + v * 32 + u);
            ay = fmaf(xv.x, wy.x, fmaf(xv.y, wy.y, fmaf(xv.z, wy.z, fmaf(xv.w, wy.w, ay))));
            as = fmaf(xv.x, ws.x, fmaf(xv.y, ws.y, fmaf(xv.z, ws.z, fmaf(xv.w, ws.w, as))));
        }
        g_y[n * 160 + t] = ay * a * INV_S32;
        g_s[n * 160 + t] = as * a * INV_S32;
    }
}

// ---------------- shared h computation for edge kernels ----------------
__device__ __forceinline__ void compute_h(float* h, const float* __restrict__ ele,
                                          const float* s_w0, int e) {
    float el[8];
    const float4* elp = reinterpret_cast<const float4*>(ele + e * 8);
    float4 ea = elp[0], eb = elp[1];
    el[0] = ea.x; el[1] = ea.y; el[2] = ea.z; el[3] = ea.w;
    el[4] = eb.x; el[5] = eb.y; el[6] = eb.z; el[7] = eb.w;
    #pragma unroll
    for (int c = 0; c < 64; c++) {
        float z = 0.f;
        #pragma unroll
        for (int k = 0; k < 8; k++) z = fmaf(el[k], s_w0[k * 64 + c], z);
        z *= INV_S8;
        float sg = __fdividef(1.f, 1.f + __expf(-z));
        h[c] = z * sg * (SILU_C_F * 0.03125f);   // fold 1/sqrt(64) * 1/sqrt(16)
    }
}

// ---------------- edge kernel A: scalar-source paths (k0, k2, k5) ----------------
__global__ __launch_bounds__(128, 4) void k_edgeA(
    const float* __restrict__ edge_attr, const float* __restrict__ ele,
    const int* __restrict__ edge_src, const int* __restrict__ edge_dst,
    const float* __restrict__ fc_w0, const float* __restrict__ fc_w1)
{
    extern __shared__ float sw[];
    float* sA = sw;               // [c][0:192] compact: 64*192
    float* s_w0 = sw + 64 * 192;  // 8*64
    int tid = threadIdx.x;
    for (int i = tid; i < 64 * 192; i += 128) {
        int c = i / 192, j = i - c * 192;
        sA[i] = fc_w1[c * 320 + j];
    }
    for (int i = tid; i < 512; i += 128) s_w0[i] = fc_w0[i];
    __syncthreads();

    int e = blockIdx.x * 128 + tid;
    float h[64];
    compute_h(h, ele, s_w0, e);

    int src = edge_src[e], dst = edge_dst[e];
    const float* ys = g_y + src * 160;
    float* ag = g_agg + dst * 960;

    float e0  = edge_attr[e * 9 + 0];
    float e1a = edge_attr[e * 9 + 1], e1b = edge_attr[e * 9 + 2], e1c = edge_attr[e * 9 + 3];
    float p0  = edge_attr[e * 9 + 4], p1 = edge_attr[e * 9 + 5], p2 = edge_attr[e * 9 + 6];
    float p3  = edge_attr[e * 9 + 7], p4 = edge_attr[e * 9 + 8];

    for (int u0 = 0; u0 < 64; u0 += 4) {
        float4 yv = *reinterpret_cast<const float4*>(ys + u0);
        float yy[4] = {yv.x, yv.y, yv.z, yv.w};
        unsigned long long wa0 = 0, wa1 = 0, wb0 = 0, wb1 = 0, wc0 = 0, wc1 = 0;
        const float* wrow = sA + u0;
        #pragma unroll
        for (int c = 0; c < 64; c++) {
            unsigned long long hh = pack2(h[c]);
            const float* r = wrow + c * 192;
            ulonglong2 q0 = *reinterpret_cast<const ulonglong2*>(r);
            ulonglong2 q1 = *reinterpret_cast<const ulonglong2*>(r + 64);
            ulonglong2 q2 = *reinterpret_cast<const ulonglong2*>(r + 128);
            fma2(wa0, hh, q0.x); fma2(wa1, hh, q0.y);
            fma2(wb0, hh, q1.x); fma2(wb1, hh, q1.y);
            fma2(wc0, hh, q2.x); fma2(wc1, hh, q2.y);
        }
        float2 a0 = unpack2(wa0), a1 = unpack2(wa1);
        float2 b0 = unpack2(wb0), b1 = unpack2(wb1);
        float2 c0 = unpack2(wc0), c1 = unpack2(wc1);
        float wa[4] = {a0.x, a0.y, a1.x, a1.y};
        float wb[4] = {b0.x, b0.y, b1.x, b1.y};
        float wc[4] = {c0.x, c0.y, c1.x, c1.y};

        red4(ag + u0, yy[0]*e0*wa[0], yy[1]*e0*wa[1], yy[2]*e0*wa[2], yy[3]*e0*wa[3]);
        {
            float t2[12];
            #pragma unroll
            for (int d = 0; d < 4; d++) {
                float base = yy[d] * wb[d];
                t2[d*3+0] = base * e1a; t2[d*3+1] = base * e1b; t2[d*3+2] = base * e1c;
            }
            red4(ag + 96 + u0*3 + 0, t2[0], t2[1], t2[2],  t2[3]);
            red4(ag + 96 + u0*3 + 4, t2[4], t2[5], t2[6],  t2[7]);
            red4(ag + 96 + u0*3 + 8, t2[8], t2[9], t2[10], t2[11]);
        }
        {
            float t5[20];
            #pragma unroll
            for (int d = 0; d < 4; d++) {
                float base = yy[d] * wc[d];
                t5[d*5+0] = base*p0; t5[d*5+1] = base*p1; t5[d*5+2] = base*p2;
                t5[d*5+3] = base*p3; t5[d*5+4] = base*p4;
            }
            red4(ag + 480 + u0*5 + 0,  t5[0],  t5[1],  t5[2],  t5[3]);
            red4(ag + 480 + u0*5 + 4,  t5[4],  t5[5],  t5[6],  t5[7]);
            red4(ag + 480 + u0*5 + 8,  t5[8],  t5[9],  t5[10], t5[11]);
            red4(ag + 480 + u0*5 + 12, t5[12], t5[13], t5[14], t5[15]);
            red4(ag + 480 + u0*5 + 16, t5[16], t5[17], t5[18], t5[19]);
        }
    }
}

// ---------------- edge kernel B: vector-source paths (k1, k3, k4, k6) ----------------
__global__ __launch_bounds__(128, 4) void k_edgeB(
    const float* __restrict__ edge_attr, const float* __restrict__ ele,
    const int* __restrict__ edge_src, const int* __restrict__ edge_dst,
    const float* __restrict__ fc_w0, const float* __restrict__ fc_w1)
{
    extern __shared__ float sw[];
    float* sB = sw;               // [c][192:320] compact: 64*128
    float* s_w0 = sw + 64 * 128;
    int tid = threadIdx.x;
    for (int i = tid; i < 64 * 128; i += 128) {
        int c = i >> 7, j = i & 127;
        sB[i] = fc_w1[c * 320 + 192 + j];
    }
    for (int i = tid; i < 512; i += 128) s_w0[i] = fc_w0[i];
    __syncthreads();

    int e = blockIdx.x * 128 + tid;
    float h[64];
    compute_h(h, ele, s_w0, e);

    int src = edge_src[e], dst = edge_dst[e];
    const float* ys = g_y + src * 160;
    float* ag = g_agg + dst * 960;

    float e0  = edge_attr[e * 9 + 0];
    float e1a = edge_attr[e * 9 + 1], e1b = edge_attr[e * 9 + 2], e1c = edge_attr[e * 9 + 3];
    float p0  = edge_attr[e * 9 + 4], p1 = edge_attr[e * 9 + 5], p2 = edge_attr[e * 9 + 6];
    float p3  = edge_attr[e * 9 + 7], p4 = edge_attr[e * 9 + 8];

    float Myy = -p2 * IS6 - p4 * IS2;
    float Mzz =  2.f * p2 * IS6;
    float Mxx = -p2 * IS6 + p4 * IS2;
    float Myz =  p1 * IS2;
    float Myx =  p0 * IS2;
    float Mzx =  p3 * IS2;

    const float* yv1 = ys + 64;
    for (int v0 = 0; v0 < 32; v0 += 4) {
        float4 q0 = *reinterpret_cast<const float4*>(yv1 + v0 * 3);
        float4 q1 = *reinterpret_cast<const float4*>(yv1 + v0 * 3 + 4);
        float4 q2 = *reinterpret_cast<const float4*>(yv1 + v0 * 3 + 8);
        float u[4][3] = {{q0.x, q0.y, q0.z}, {q0.w, q1.x, q1.y},
                         {q1.z, q1.w, q2.x}, {q2.y, q2.z, q2.w}};
        unsigned long long wC0=0,wC1=0,wD0=0,wD1=0,wE0=0,wE1=0,wF0=0,wF1=0;
        const float* wrow = sB + v0;
        #pragma unroll
        for (int c = 0; c < 64; c++) {
            unsigned long long hh = pack2(h[c]);
            const float* r = wrow + c * 128;
            ulonglong2 a  = *reinterpret_cast<const ulonglong2*>(r);        // w3
            ulonglong2 b  = *reinterpret_cast<const ulonglong2*>(r + 32);   // w1
            ulonglong2 cc = *reinterpret_cast<const ulonglong2*>(r + 64);   // w6
            ulonglong2 dd = *reinterpret_cast<const ulonglong2*>(r + 96);   // w4
            fma2(wC0, hh, a.x);  fma2(wC1, hh, a.y);
            fma2(wD0, hh, b.x);  fma2(wD1, hh, b.y);
            fma2(wE0, hh, cc.x); fma2(wE1, hh, cc.y);
            fma2(wF0, hh, dd.x); fma2(wF1, hh, dd.y);
        }
        float2 C0=unpack2(wC0), C1=unpack2(wC1), D0=unpack2(wD0), D1=unpack2(wD1);
        float2 E0=unpack2(wE0), E1=unpack2(wE1), F0=unpack2(wF0), F1=unpack2(wF1);
        float wC[4]={C0.x,C0.y,C1.x,C1.y}, wD[4]={D0.x,D0.y,D1.x,D1.y};
        float wE[4]={E0.x,E0.y,E1.x,E1.y}, wF[4]={F0.x,F0.y,F1.x,F1.y};

        {
            float k1v[4];
            #pragma unroll
            for (int d = 0; d < 4; d++)
                k1v[d] = INV_S3 * wD[d] * (u[d][0]*e1a + u[d][1]*e1b + u[d][2]*e1c);
            red4(ag + 64 + v0, k1v[0], k1v[1], k1v[2], k1v[3]);
        }
        {
            float t3[12];
            #pragma unroll
            for (int d = 0; d < 4; d++) {
                float base = e0 * wC[d];
                t3[d*3+0] = base*u[d][0]; t3[d*3+1] = base*u[d][1]; t3[d*3+2] = base*u[d][2];
            }
            red4(ag + 288 + v0*3 + 0, t3[0], t3[1], t3[2],  t3[3]);
            red4(ag + 288 + v0*3 + 4, t3[4], t3[5], t3[6],  t3[7]);
            red4(ag + 288 + v0*3 + 8, t3[8], t3[9], t3[10], t3[11]);
        }
        {
            float t4[12];
            #pragma unroll
            for (int d = 0; d < 4; d++) {
                float uy = u[d][0], uz = u[d][1], ux = u[d][2];
                float s = S3_DIV_S5 * wF[d];
                t4[d*3+0] = s * (Myy*uy + Myz*uz + Myx*ux);
                t4[d*3+1] = s * (Myz*uy + Mzz*uz + Mzx*ux);
                t4[d*3+2] = s * (Myx*uy + Mzx*uz + Mxx*ux);
            }
            red4(ag + 384 + v0*3 + 0, t4[0], t4[1], t4[2],  t4[3]);
            red4(ag + 384 + v0*3 + 4, t4[4], t4[5], t4[6],  t4[7]);
            red4(ag + 384 + v0*3 + 8, t4[8], t4[9], t4[10], t4[11]);
        }
        {
            float t6[20];
            #pragma unroll
            for (int d = 0; d < 4; d++) {
                float uy = u[d][0], uz = u[d][1], ux = u[d][2];
                float s = -wE[d];
                t6[d*5+0] = s * ((ux*e1a + uy*e1c) * IS2);
                t6[d*5+1] = s * ((uy*e1b + uz*e1a) * IS2);
                t6[d*5+2] = s * ((-uy*e1a + 2.f*uz*e1b - ux*e1c) * IS6);
                t6[d*5+3] = s * ((uz*e1c + ux*e1b) * IS2);
                t6[d*5+4] = s * ((-uy*e1a + ux*e1c) * IS2);
            }
            red4(ag + 800 + v0*5 + 0,  t6[0],  t6[1],  t6[2],  t6[3]);
            red4(ag + 800 + v0*5 + 4,  t6[4],  t6[5],  t6[6],  t6[7]);
            red4(ag + 800 + v0*5 + 8,  t6[8],  t6[9],  t6[10], t6[11]);
            red4(ag + 800 + v0*5 + 12, t6[12], t6[13], t6[14], t6[15]);
            red4(ag + 800 + v0*5 + 16, t6[16], t6[17], t6[18], t6[19]);
        }
    }
}

// ---------------- node post-linear (lin2) + combine ----------------
__global__ __launch_bounds__(320) void k_out(
    const float* __restrict__ node_attr, float* __restrict__ out)
{
    __shared__ float m[960];
    __shared__ float sv[160];
    __shared__ float m1T[3 * 128];
    __shared__ float m2T[5 * 96];
    int n = blockIdx.x, t = threadIdx.x;
    {
        const float4* a4 = reinterpret_cast<const float4*>(g_agg + n * 960);
        float4* m4 = reinterpret_cast<float4*>(m);
        if (t < 240) m4[t] = a4[t];
        if (t < 160) sv[t] = g_s[n * 160 + t];
    }
    __syncthreads();
    for (int idx = t; idx < 384; idx += 320) {
        int i = idx >> 7, p = idx & 127;
        m1T[idx] = m[96 + p * 3 + i];
    }
    for (int idx = t; idx < 480; idx += 320) {
        int i = idx / 96, p = idx - i * 96;
        m2T[idx] = m[480 + p * 5 + i];
    }
    __syncthreads();
    float a = node_attr[n];
    if (t < 64) {
        float acc = 0.f;
        #pragma unroll
        for (int p = 0; p < 96; p += 4) {
            float4 mv = *reinterpret_cast<const float4*>(m + p);
            float4 wv = *reinterpret_cast<const float4*>(g_w0T + t * 96 + p);
            acc = fmaf(mv.x, wv.x, fmaf(mv.y, wv.y, fmaf(mv.z, wv.z, fmaf(mv.w, wv.w, acc))));
        }
        out[n * 320 + t] = C_S * sv[t] + C_X * (acc * a * INV_S96);
    } else if (t < 160) {
        int j = t - 64, v = j / 3, i = j - 3 * v;
        float acc = 0.f;
        #pragma unroll
        for (int p = 0; p < 128; p += 4) {
            float4 mv = *reinterpret_cast<const float4*>(m1T + i * 128 + p);
            float4 wv = *reinterpret_cast<const float4*>(g_w1T + v * 128 + p);
            acc = fmaf(mv.x, wv.x, fmaf(mv.y, wv.y, fmaf(mv.z, wv.z, fmaf(mv.w, wv.w, acc))));
        }
        out[n * 320 + t] = C_S * sv[t] + C_X * (acc * a * INV_S128);
    } else {
        int j = t - 160, v = j / 5, i = j - 5 * v;
        float acc = 0.f;
        #pragma unroll
        for (int p = 0; p < 96; p += 4) {
            float4 mv = *reinterpret_cast<const float4*>(m2T + i * 96 + p);
            float4 wv = *reinterpret_cast<const float4*>(g_w2T + v * 96 + p);
            acc = fmaf(mv.x, wv.x, fmaf(mv.y, wv.y, fmaf(mv.z, wv.z, fmaf(mv.w, wv.w, acc))));
        }
        out[n * 320 + t] = acc * a * INV_S96;
    }
}

extern "C" void kernel_launch(void* const* d_in, const int* in_sizes, int n_in,
                              void* d_out, int out_size)
{
    const float* node_input = (const float*)d_in[0];
    const float* node_attr  = (const float*)d_in[1];
    const int*   edge_src   = (const int*)  d_in[2];
    const int*   edge_dst   = (const int*)  d_in[3];
    const float* edge_attr  = (const float*)d_in[4];
    const float* ele        = (const float*)d_in[5];
    const float* sc_w0      = (const float*)d_in[6];
    const float* sc_w1      = (const float*)d_in[7];
    const float* lin1_w0    = (const float*)d_in[8];
    const float* lin1_w1    = (const float*)d_in[9];
    const float* fc_w0      = (const float*)d_in[10];
    const float* fc_w1      = (const float*)d_in[11];
    const float* lin2_w0    = (const float*)d_in[12];
    const float* lin2_w1    = (const float*)d_in[13];
    const float* lin2_w2    = (const float*)d_in[14];
    float* out = (float*)d_out;

    const int smemA = (64 * 192 + 512) * 4;   // ~51 KB
    const int smemB = (64 * 128 + 512) * 4;   // ~34 KB
    cudaFuncSetAttribute(k_edgeA, cudaFuncAttributeMaxDynamicSharedMemorySize, smemA);
    cudaFuncSetAttribute(k_edgeB, cudaFuncAttributeMaxDynamicSharedMemorySize, smemB);

    k_zero<<<(NN * 960 / 4 + 255) / 256, 256>>>();
    k_tw<<<(23552 + 255) / 256, 256>>>(lin2_w0, lin2_w1, lin2_w2, lin1_w0, lin1_w1, sc_w0, sc_w1);
    k_node<<<NN, 160>>>(node_input, node_attr);
    k_edgeA<<<NE / 128, 128, smemA>>>(edge_attr, ele, edge_src, edge_dst, fc_w0, fc_w1);
    k_edgeB<<<NE / 128, 128, smemB>>>(edge_attr, ele, edge_src, edge_dst, fc_w0, fc_w1);
    k_out<<<NN, 320>>>(node_attr, out);
}